// round 1
// baseline (speedup 1.0000x reference)
#include <cuda_runtime.h>
#include <math.h>

#define T_STEPS 2048
#define ISZ 256
#define HSZ 512
#define BSZ 64
#define NB 128
#define TPB 256
#define BN_EPS 1e-5f

// ---------------- shared memory layout ----------------
struct __align__(16) Smem {
    float buf[HSZ * BSZ];        // 32768 floats: x tile (lower 16K) / h tile (32K)
    float red[4 * 1024];         // k-slice partials
    float Whh[16 * 516];         // 16 gate rows, padded stride 516
    float Wih[16 * 260];         // 16 gate rows, padded stride 260
    float aRed[1024];            // reduced a = Whh@h   (16 rows x 64 cols)
    float bRed[1024];            // reduced b = Wih@x_t
    float sa_scale[16], sa_shift[16], sb_scale[16], sb_shift[16];
    float bias16[16], gi[16], bi[16], gh[16], bh[16];
    float gc[4], bc[4];
    float csum[8], csq[8];
    float cscale[4], cshift[4];
};

// ---------------- device globals (no allocation allowed) ----------------
__device__ float g_h[2][HSZ * BSZ];
__device__ unsigned long long g_arrive = 0ULL;        // monotonic ticket counter
__device__ volatile unsigned long long g_release = 0ULL;

// ---------------- helpers ----------------
__device__ __forceinline__ unsigned long long dup2(float w) {
    unsigned long long r;
    unsigned u = __float_as_uint(w);
    asm("mov.b64 %0, {%1, %1};" : "=l"(r) : "r"(u));
    return r;
}
__device__ __forceinline__ void fma2(unsigned long long& d, unsigned long long a,
                                     unsigned long long b) {
    asm("fma.rn.f32x2 %0, %1, %2, %0;" : "+l"(d) : "l"(a), "l"(b));
}
__device__ __forceinline__ void cp_async16(void* smem_dst, const void* gsrc) {
    unsigned s = (unsigned)__cvta_generic_to_shared(smem_dst);
    asm volatile("cp.async.cg.shared.global [%0], [%1], 16;" :: "r"(s), "l"(gsrc));
}
__device__ __forceinline__ void cp_commit() { asm volatile("cp.async.commit_group;"); }
template <int N>
__device__ __forceinline__ void cp_wait() { asm volatile("cp.async.wait_group %0;" :: "n"(N)); }

__device__ __forceinline__ float sigm(float x) { return 1.0f / (1.0f + expf(-x)); }

// ticket grid barrier: monotonic across graph replays, no resets needed
__device__ __forceinline__ void grid_barrier() {
    __syncthreads();
    if (threadIdx.x == 0) {
        __threadfence();
        unsigned long long a = atomicAdd(&g_arrive, 1ULL);
        unsigned long long target = (a / NB + 1ULL) * NB;
        if (a % NB == NB - 1) {
            __threadfence();
            g_release = target;
        } else {
            while (g_release < target) { }
        }
    }
    __syncthreads();
}

// ---------------- kernel ----------------
__global__ void __launch_bounds__(TPB, 1)
bn_lstm_kernel(const float* __restrict__ x,
               const float* __restrict__ wih,
               const float* __restrict__ whh,
               const float* __restrict__ bias,
               const float* __restrict__ gih, const float* __restrict__ bih,
               const float* __restrict__ ghh, const float* __restrict__ bhh,
               const float* __restrict__ gcc, const float* __restrict__ bcc,
               float* __restrict__ out)
{
    extern __shared__ char smem_raw[];
    Smem& s = *reinterpret_cast<Smem*>(smem_raw);

    const int tid = threadIdx.x;
    const int bid = blockIdx.x;
    const int j0  = 4 * bid;          // first hidden row owned by this block

    // dot-phase mapping
    const int ks   = tid >> 6;        // k-slice 0..3
    const int sx   = tid & 63;
    const int colg = sx & 7;          // column group (cols 2*colg+16*m, +1)
    const int rowg = sx >> 3;         // 0..7
    const int r0   = rowg * 2;        // local gate rows
    const int r1   = r0 + 1;
    // epilogue mapping
    const int col = tid & 63;
    const int jj  = tid >> 6;         // local hidden row 0..3

    // ---------- init: weights to SMEM, params, zero h[0] ----------
    for (int i = tid; i < 16 * 512; i += TPB) {
        int r = i >> 9, k = i & 511;
        int grow = 512 * (r >> 2) + j0 + (r & 3);
        s.Whh[r * 516 + k] = whh[(size_t)grow * 512 + k];
    }
    for (int i = tid; i < 16 * 256; i += TPB) {
        int r = i >> 8, k = i & 255;
        int grow = 512 * (r >> 2) + j0 + (r & 3);
        s.Wih[r * 260 + k] = wih[(size_t)grow * 256 + k];
    }
    if (tid < 16) {
        int grow = 512 * (tid >> 2) + j0 + (tid & 3);
        s.bias16[tid] = bias[grow];
        s.gi[tid] = gih[grow]; s.bi[tid] = bih[grow];
        s.gh[tid] = ghh[grow]; s.bh[tid] = bhh[grow];
    }
    if (tid < 4) { s.gc[tid] = gcc[j0 + tid]; s.bc[tid] = bcc[j0 + tid]; }
    // zero h buffer 0 (own rows): 4 rows x 64 cols = 256 entries
    g_h[0][(j0 + (tid >> 6)) * BSZ + (tid & 63)] = 0.0f;

    float c_reg = 0.0f;

    grid_barrier();

    // ---------- time loop ----------
    for (int t = 0; t < T_STEPS; ++t) {
        const int p = t & 1;
        const float* __restrict__ hsrc = g_h[p];

        // async load x_t (lower 16K floats of buf) and h upper half
        {
            const float* xg = x + (size_t)t * (ISZ * BSZ);
            #pragma unroll
            for (int i = 0; i < 16; ++i) {
                int o = (tid + i * TPB) * 4;            // 0..16383
                cp_async16(&s.buf[o], xg + o);
            }
            cp_commit();
            #pragma unroll
            for (int i = 0; i < 16; ++i) {
                int o = 16384 + (tid + i * TPB) * 4;    // h rows 256..511
                cp_async16(&s.buf[o], hsrc + o);
            }
            cp_commit();
        }
        cp_wait<1>();          // x ready (h-upper may still be in flight)
        __syncthreads();

        // ---------- x-phase: b = Wih @ x_t (k-slice of 64) ----------
        unsigned long long acc[2][4];
        #pragma unroll
        for (int i = 0; i < 2; ++i)
            #pragma unroll
            for (int m = 0; m < 4; ++m) acc[i][m] = 0ULL;
        {
            const int kb = ks * 64;
            const float* w0p = s.Wih + r0 * 260 + kb;
            const float* w1p = w0p + 260;
            const unsigned long long* hp =
                (const unsigned long long*)(s.buf + kb * BSZ) + colg;
            #pragma unroll 4
            for (int k = 0; k < 64; ++k) {
                unsigned long long w0 = dup2(w0p[k]);
                unsigned long long w1 = dup2(w1p[k]);
                unsigned long long v0 = hp[0], v1 = hp[8], v2 = hp[16], v3 = hp[24];
                fma2(acc[0][0], w0, v0); fma2(acc[0][1], w0, v1);
                fma2(acc[0][2], w0, v2); fma2(acc[0][3], w0, v3);
                fma2(acc[1][0], w1, v0); fma2(acc[1][1], w1, v1);
                fma2(acc[1][2], w1, v2); fma2(acc[1][3], w1, v3);
                hp += 32;
            }
        }
        __syncthreads();    // x reads done -> lower buf reusable

        // async load h lower half (overlaps b reduction)
        #pragma unroll
        for (int i = 0; i < 16; ++i) {
            int o = (tid + i * TPB) * 4;
            cp_async16(&s.buf[o], hsrc + o);
        }
        cp_commit();

        // store b partials, reduce over 4 k-slices
        {
            unsigned long long* redU = (unsigned long long*)s.red;
            #pragma unroll
            for (int m = 0; m < 4; ++m) {
                redU[ks * 512 + r0 * 32 + colg + 8 * m] = acc[0][m];
                redU[ks * 512 + r1 * 32 + colg + 8 * m] = acc[1][m];
            }
        }
        __syncthreads();
        {
            float4 p0 = *(const float4*)&s.red[4 * tid];
            float4 p1 = *(const float4*)&s.red[1024 + 4 * tid];
            float4 p2 = *(const float4*)&s.red[2048 + 4 * tid];
            float4 p3 = *(const float4*)&s.red[3072 + 4 * tid];
            float4 rr;
            rr.x = p0.x + p1.x + p2.x + p3.x;
            rr.y = p0.y + p1.y + p2.y + p3.y;
            rr.z = p0.z + p1.z + p2.z + p3.z;
            rr.w = p0.w + p1.w + p2.w + p3.w;
            *(float4*)&s.bRed[4 * tid] = rr;
        }
        cp_wait<0>();
        __syncthreads();    // full h in buf, red consumable again

        // ---------- h-phase: a = Whh @ h (k-slice of 128) ----------
        #pragma unroll
        for (int i = 0; i < 2; ++i)
            #pragma unroll
            for (int m = 0; m < 4; ++m) acc[i][m] = 0ULL;
        {
            const int kb = ks * 128;
            const float* w0p = s.Whh + r0 * 516 + kb;
            const float* w1p = w0p + 516;
            const unsigned long long* hp =
                (const unsigned long long*)(s.buf + kb * BSZ) + colg;
            #pragma unroll 4
            for (int k = 0; k < 128; ++k) {
                unsigned long long w0 = dup2(w0p[k]);
                unsigned long long w1 = dup2(w1p[k]);
                unsigned long long v0 = hp[0], v1 = hp[8], v2 = hp[16], v3 = hp[24];
                fma2(acc[0][0], w0, v0); fma2(acc[0][1], w0, v1);
                fma2(acc[0][2], w0, v2); fma2(acc[0][3], w0, v3);
                fma2(acc[1][0], w1, v0); fma2(acc[1][1], w1, v1);
                fma2(acc[1][2], w1, v2); fma2(acc[1][3], w1, v3);
                hp += 32;
            }
        }
        __syncthreads();
        {
            unsigned long long* redU = (unsigned long long*)s.red;
            #pragma unroll
            for (int m = 0; m < 4; ++m) {
                redU[ks * 512 + r0 * 32 + colg + 8 * m] = acc[0][m];
                redU[ks * 512 + r1 * 32 + colg + 8 * m] = acc[1][m];
            }
        }
        __syncthreads();
        {
            float4 p0 = *(const float4*)&s.red[4 * tid];
            float4 p1 = *(const float4*)&s.red[1024 + 4 * tid];
            float4 p2 = *(const float4*)&s.red[2048 + 4 * tid];
            float4 p3 = *(const float4*)&s.red[3072 + 4 * tid];
            float4 rr;
            rr.x = p0.x + p1.x + p2.x + p3.x;
            rr.y = p0.y + p1.y + p2.y + p3.y;
            rr.z = p0.z + p1.z + p2.z + p3.z;
            rr.w = p0.w + p1.w + p2.w + p3.w;
            *(float4*)&s.aRed[4 * tid] = rr;
        }
        __syncthreads();

        // ---------- BN stats for a and b (warp w -> rows 2w, 2w+1) ----------
        {
            int w = tid >> 5, lane = tid & 31;
            #pragma unroll
            for (int rr = 0; rr < 2; ++rr) {
                int r = 2 * w + rr;
                float a0 = s.aRed[r * 64 + lane], a1 = s.aRed[r * 64 + 32 + lane];
                float b0 = s.bRed[r * 64 + lane], b1 = s.bRed[r * 64 + 32 + lane];
                float sa = a0 + a1, qa = a0 * a0 + a1 * a1;
                float sb = b0 + b1, qb = b0 * b0 + b1 * b1;
                #pragma unroll
                for (int off = 16; off; off >>= 1) {
                    sa += __shfl_xor_sync(0xffffffffu, sa, off);
                    qa += __shfl_xor_sync(0xffffffffu, qa, off);
                    sb += __shfl_xor_sync(0xffffffffu, sb, off);
                    qb += __shfl_xor_sync(0xffffffffu, qb, off);
                }
                if (lane == 0) {
                    float mu = sa * (1.0f / 64.0f);
                    float var = qa * (1.0f / 64.0f) - mu * mu;
                    float rs = rsqrtf(var + BN_EPS);
                    float sc = rs * s.gh[r];
                    s.sa_scale[r] = sc; s.sa_shift[r] = s.bh[r] - mu * sc;
                    mu = sb * (1.0f / 64.0f);
                    var = qb * (1.0f / 64.0f) - mu * mu;
                    rs = rsqrtf(var + BN_EPS);
                    sc = rs * s.gi[r];
                    s.sb_scale[r] = sc; s.sb_shift[r] = s.bi[r] - mu * sc;
                }
            }
        }
        __syncthreads();

        // ---------- gates, cell update, BN(c), h ----------
        float pre[4];
        #pragma unroll
        for (int g = 0; g < 4; ++g) {
            int l = g * 4 + jj;
            float av = s.aRed[l * 64 + col] * s.sa_scale[l] + s.sa_shift[l];
            float bv = s.bRed[l * 64 + col] * s.sb_scale[l] + s.sb_shift[l];
            pre[g] = av + bv + s.bias16[l];
        }
        float gi_ = sigm(pre[0]);
        float gf_ = sigm(pre[1]);
        float gg_ = tanhf(pre[2]);
        float go_ = sigm(pre[3]);
        float cn = gf_ * c_reg + gi_ * gg_;
        c_reg = cn;

        // BN stats of c over batch (row jj spans 2 warps)
        {
            float s1 = cn, s2 = cn * cn;
            #pragma unroll
            for (int off = 16; off; off >>= 1) {
                s1 += __shfl_xor_sync(0xffffffffu, s1, off);
                s2 += __shfl_xor_sync(0xffffffffu, s2, off);
            }
            int w = tid >> 5;
            if ((tid & 31) == 0) { s.csum[w] = s1; s.csq[w] = s2; }
        }
        __syncthreads();
        if (tid < 4) {
            float S = s.csum[2 * tid] + s.csum[2 * tid + 1];
            float Q = s.csq[2 * tid] + s.csq[2 * tid + 1];
            float mu = S * (1.0f / 64.0f);
            float var = Q * (1.0f / 64.0f) - mu * mu;
            float rs = rsqrtf(var + BN_EPS);
            float sc = rs * s.gc[tid];
            s.cscale[tid] = sc; s.cshift[tid] = s.bc[tid] - mu * sc;
        }
        __syncthreads();

        float hv = go_ * tanhf(cn * s.cscale[jj] + s.cshift[jj]);
        int hrow = j0 + jj;
        g_h[1 - p][hrow * BSZ + col] = hv;
        out[(size_t)t * (HSZ * BSZ) + hrow * BSZ + col] = hv;

        grid_barrier();
    }
}

// ---------------- launch ----------------
extern "C" void kernel_launch(void* const* d_in, const int* in_sizes, int n_in,
                              void* d_out, int out_size) {
    const float* x    = (const float*)d_in[0];
    const float* wih  = (const float*)d_in[1];
    const float* whh  = (const float*)d_in[2];
    const float* bias = (const float*)d_in[3];
    const float* gih  = (const float*)d_in[4];
    const float* bih  = (const float*)d_in[5];
    const float* ghh  = (const float*)d_in[6];
    const float* bhh  = (const float*)d_in[7];
    const float* gcc  = (const float*)d_in[8];
    const float* bcc  = (const float*)d_in[9];
    float* out = (float*)d_out;

    cudaFuncSetAttribute(bn_lstm_kernel,
                         cudaFuncAttributeMaxDynamicSharedMemorySize,
                         (int)sizeof(Smem));
    bn_lstm_kernel<<<NB, TPB, sizeof(Smem)>>>(x, wih, whh, bias, gih, bih,
                                              ghh, bhh, gcc, bcc, out);
}

// round 3
// speedup vs baseline: 1.2756x; 1.2756x over previous
#include <cuda_runtime.h>
#include <math.h>

#define T_STEPS 2048
#define ISZ 256
#define HSZ 512
#define BSZ 64
#define NB 128
#define TPB 256
#define KS 8
#define BN_EPS 1e-5f

#define WIH_STR 264   // 256+8: 8 mod 32 banks, 16B aligned
#define WHH_STR 520   // 512+8

typedef unsigned long long ull;

// ---------------- shared memory layout ----------------
struct __align__(16) Smem {
    float buf[HSZ * BSZ];        // 131072 B: x tile (lower half) / h tile
    float red[KS * 1024];        // 32768 B: per-kslice partials (permuted layout)
    float Whh[16 * WHH_STR];     // 33280 B
    float Wih[16 * WIH_STR];     // 16896 B
    float aRed[1024];            // natural [row16][col64]
    float bRed[1024];
    float sa_scale[16], sa_shift[16], sb_scale[16], sb_shift[16];
    float bias16[16], gi[16], bi[16], gh[16], bh[16];
    float gc[4], bc[4];
    float csum[8], csq[8];
    float cscale[4], cshift[4];
};

// ---------------- device globals ----------------
__device__ float g_h[2][HSZ * BSZ];
__device__ unsigned long long g_arrive = 0ULL;
__device__ volatile unsigned long long g_release = 0ULL;

// ---------------- helpers ----------------
__device__ __forceinline__ ull dup2(float w) {
    ull r;
    unsigned u = __float_as_uint(w);
    asm("mov.b64 %0, {%1, %1};" : "=l"(r) : "r"(u));
    return r;
}
__device__ __forceinline__ void fma2(ull& d, ull a, ull b) {
    asm("fma.rn.f32x2 %0, %1, %2, %0;" : "+l"(d) : "l"(a), "l"(b));
}
__device__ __forceinline__ void cp_async16(void* smem_dst, const void* gsrc) {
    unsigned s = (unsigned)__cvta_generic_to_shared(smem_dst);
    asm volatile("cp.async.cg.shared.global [%0], [%1], 16;" :: "r"(s), "l"(gsrc));
}
__device__ __forceinline__ void cp_commit() { asm volatile("cp.async.commit_group;"); }
template <int N>
__device__ __forceinline__ void cp_wait() { asm volatile("cp.async.wait_group %0;" :: "n"(N)); }

__device__ __forceinline__ float sigm(float x) { return 1.0f / (1.0f + expf(-x)); }

__device__ __forceinline__ void grid_barrier() {
    __syncthreads();
    if (threadIdx.x == 0) {
        __threadfence();
        unsigned long long a = atomicAdd(&g_arrive, 1ULL);
        unsigned long long target = (a / NB + 1ULL) * NB;
        if (a % NB == NB - 1) {
            __threadfence();
            g_release = target;
        } else {
            while (g_release < target) { }
        }
    }
    __syncthreads();
}

// GEMM micro-kernel: acc[ri][m] += W[row(ri)][kb+k] * v[kb+k][cp(m)]
// rows: rowg + 4*ri, colpairs: colg + 8*m
template <int KLEN, int WSTR>
__device__ __forceinline__ void dot_phase(ull acc[4][4], const float* __restrict__ W,
                                          const float* __restrict__ vsrc,
                                          int kb, int rowg, int colg)
{
    const float* w0p = W + (rowg + 0)  * WSTR + kb;
    const float* w1p = W + (rowg + 4)  * WSTR + kb;
    const float* w2p = W + (rowg + 8)  * WSTR + kb;
    const float* w3p = W + (rowg + 12) * WSTR + kb;
    const ull* vb = (const ull*)vsrc + (size_t)kb * 32 + colg;
    #pragma unroll 2
    for (int k4 = 0; k4 < KLEN; k4 += 4) {
        float4 w0 = *(const float4*)(w0p + k4);
        float4 w1 = *(const float4*)(w1p + k4);
        float4 w2 = *(const float4*)(w2p + k4);
        float4 w3 = *(const float4*)(w3p + k4);
        const float* f0 = (const float*)&w0;
        const float* f1 = (const float*)&w1;
        const float* f2 = (const float*)&w2;
        const float* f3 = (const float*)&w3;
        #pragma unroll
        for (int kk = 0; kk < 4; ++kk) {
            const ull* vp = vb + (size_t)(k4 + kk) * 32;
            ull v0 = vp[0], v1 = vp[8], v2 = vp[16], v3 = vp[24];
            ull d0 = dup2(f0[kk]);
            ull d1 = dup2(f1[kk]);
            ull d2 = dup2(f2[kk]);
            ull d3 = dup2(f3[kk]);
            fma2(acc[0][0], d0, v0); fma2(acc[0][1], d0, v1);
            fma2(acc[0][2], d0, v2); fma2(acc[0][3], d0, v3);
            fma2(acc[1][0], d1, v0); fma2(acc[1][1], d1, v1);
            fma2(acc[1][2], d1, v2); fma2(acc[1][3], d1, v3);
            fma2(acc[2][0], d2, v0); fma2(acc[2][1], d2, v1);
            fma2(acc[2][2], d2, v2); fma2(acc[2][3], d2, v3);
            fma2(acc[3][0], d3, v0); fma2(acc[3][1], d3, v1);
            fma2(acc[3][2], d3, v2); fma2(acc[3][3], d3, v3);
        }
    }
}

__device__ __forceinline__ void store_partials(Smem& s, ull acc[4][4], int ksl, int lane) {
    ull* redU = (ull*)s.red;
    #pragma unroll
    for (int ri = 0; ri < 4; ++ri)
        #pragma unroll
        for (int m = 0; m < 4; ++m)
            redU[ksl * 512 + (ri * 4 + m) * 32 + lane] = acc[ri][m];
}

// reduce KS slices into natural layout dst[row*64 + col]; thread -> 4 floats
__device__ __forceinline__ void reduce_partials(Smem& s, float* dst, int tid) {
    int l = tid >> 4;                 // local row 0..15
    int cp0 = (tid & 15) * 2;         // first colpair (even)
    // permuted slot (ull units): ((l>>2)*4 + (cp0>>3))*32 + (l&3)*8 + (cp0&7)
    int slot = (((l >> 2) * 4 + (cp0 >> 3)) * 32 + (l & 3) * 8 + (cp0 & 7));
    const float4* rp = (const float4*)s.red;
    int f4 = slot >> 1;               // slot is even -> float4 index
    float4 a = rp[f4];
    #pragma unroll
    for (int ss = 1; ss < KS; ++ss) {
        float4 p = rp[ss * 256 + f4];
        a.x += p.x; a.y += p.y; a.z += p.z; a.w += p.w;
    }
    *(float4*)&dst[4 * tid] = a;
}

// ---------------- kernel ----------------
__global__ void __launch_bounds__(TPB, 1)
bn_lstm_kernel(const float* __restrict__ x,
               const float* __restrict__ wih,
               const float* __restrict__ whh,
               const float* __restrict__ bias,
               const float* __restrict__ gih, const float* __restrict__ bih,
               const float* __restrict__ ghh, const float* __restrict__ bhh,
               const float* __restrict__ gcc, const float* __restrict__ bcc,
               float* __restrict__ out)
{
    extern __shared__ char smem_raw[];
    Smem& s = *reinterpret_cast<Smem*>(smem_raw);

    const int tid = threadIdx.x;
    const int bid = blockIdx.x;
    const int j0  = 4 * bid;

    // dot-phase mapping: warp = k-slice, lane -> (rowg, colg)
    const int ksl  = tid >> 5;
    const int lane = tid & 31;
    const int colg = lane & 7;
    const int rowg = lane >> 3;
    // epilogue mapping
    const int col = tid & 63;
    const int jj  = tid >> 6;

    // ---------- init ----------
    for (int i = tid; i < 16 * 512; i += TPB) {
        int r = i >> 9, k = i & 511;
        int grow = 512 * (r >> 2) + j0 + (r & 3);
        s.Whh[r * WHH_STR + k] = whh[(size_t)grow * 512 + k];
    }
    for (int i = tid; i < 16 * 256; i += TPB) {
        int r = i >> 8, k = i & 255;
        int grow = 512 * (r >> 2) + j0 + (r & 3);
        s.Wih[r * WIH_STR + k] = wih[(size_t)grow * 256 + k];
    }
    if (tid < 16) {
        int grow = 512 * (tid >> 2) + j0 + (tid & 3);
        s.bias16[tid] = bias[grow];
        s.gi[tid] = gih[grow]; s.bi[tid] = bih[grow];
        s.gh[tid] = ghh[grow]; s.bh[tid] = bhh[grow];
    }
    if (tid < 4) { s.gc[tid] = gcc[j0 + tid]; s.bc[tid] = bcc[j0 + tid]; }
    g_h[0][(j0 + jj) * BSZ + col] = 0.0f;

    float c_reg = 0.0f;

    grid_barrier();

    // ---------- time loop ----------
    for (int t = 0; t < T_STEPS; ++t) {
        const int p = t & 1;
        const float* __restrict__ hsrc = g_h[p];

        // async: x_t (buf lower 64KB), h upper half (buf upper 64KB)
        {
            const float* xg = x + (size_t)t * (ISZ * BSZ);
            #pragma unroll
            for (int i = 0; i < 16; ++i) {
                int o = (tid + i * TPB) * 4;
                cp_async16(&s.buf[o], xg + o);
            }
            cp_commit();
            #pragma unroll
            for (int i = 0; i < 16; ++i) {
                int o = 16384 + (tid + i * TPB) * 4;
                cp_async16(&s.buf[o], hsrc + o);
            }
            cp_commit();
        }
        cp_wait<1>();
        __syncthreads();

        // ---------- x-phase: b = Wih @ x_t ----------
        ull acc[4][4];
        #pragma unroll
        for (int i = 0; i < 4; ++i)
            #pragma unroll
            for (int m = 0; m < 4; ++m) acc[i][m] = 0ULL;
        dot_phase<ISZ / KS, WIH_STR>(acc, s.Wih, s.buf, ksl * (ISZ / KS), rowg, colg);
        __syncthreads();          // x reads done -> lower buf reusable

        // async: h lower half (overlaps b reduction)
        #pragma unroll
        for (int i = 0; i < 16; ++i) {
            int o = (tid + i * TPB) * 4;
            cp_async16(&s.buf[o], hsrc + o);
        }
        cp_commit();

        store_partials(s, acc, ksl, lane);
        __syncthreads();
        reduce_partials(s, s.bRed, tid);
        cp_wait<0>();
        __syncthreads();          // full h present, red consumable again

        // ---------- h-phase: a = Whh @ h ----------
        #pragma unroll
        for (int i = 0; i < 4; ++i)
            #pragma unroll
            for (int m = 0; m < 4; ++m) acc[i][m] = 0ULL;
        dot_phase<HSZ / KS, WHH_STR>(acc, s.Whh, s.buf, ksl * (HSZ / KS), rowg, colg);
        __syncthreads();
        store_partials(s, acc, ksl, lane);
        __syncthreads();
        reduce_partials(s, s.aRed, tid);
        __syncthreads();

        // ---------- BN stats for a and b (warp w -> rows 2w, 2w+1) ----------
        {
            int w = tid >> 5, ln = tid & 31;
            #pragma unroll
            for (int rr = 0; rr < 2; ++rr) {
                int r = 2 * w + rr;
                float a0 = s.aRed[r * 64 + ln], a1 = s.aRed[r * 64 + 32 + ln];
                float b0 = s.bRed[r * 64 + ln], b1 = s.bRed[r * 64 + 32 + ln];
                float sa = a0 + a1, qa = a0 * a0 + a1 * a1;
                float sb = b0 + b1, qb = b0 * b0 + b1 * b1;
                #pragma unroll
                for (int off = 16; off; off >>= 1) {
                    sa += __shfl_xor_sync(0xffffffffu, sa, off);
                    qa += __shfl_xor_sync(0xffffffffu, qa, off);
                    sb += __shfl_xor_sync(0xffffffffu, sb, off);
                    qb += __shfl_xor_sync(0xffffffffu, qb, off);
                }
                if (ln == 0) {
                    float mu = sa * (1.0f / 64.0f);
                    float var = qa * (1.0f / 64.0f) - mu * mu;
                    float rs = rsqrtf(var + BN_EPS);
                    float sc = rs * s.gh[r];
                    s.sa_scale[r] = sc; s.sa_shift[r] = s.bh[r] - mu * sc;
                    mu = sb * (1.0f / 64.0f);
                    var = qb * (1.0f / 64.0f) - mu * mu;
                    rs = rsqrtf(var + BN_EPS);
                    sc = rs * s.gi[r];
                    s.sb_scale[r] = sc; s.sb_shift[r] = s.bi[r] - mu * sc;
                }
            }
        }
        __syncthreads();

        // ---------- gates, cell update, BN(c), h ----------
        float pre[4];
        #pragma unroll
        for (int g = 0; g < 4; ++g) {
            int l = g * 4 + jj;
            float av = s.aRed[l * 64 + col] * s.sa_scale[l] + s.sa_shift[l];
            float bv = s.bRed[l * 64 + col] * s.sb_scale[l] + s.sb_shift[l];
            pre[g] = av + bv + s.bias16[l];
        }
        float gi_ = sigm(pre[0]);
        float gf_ = sigm(pre[1]);
        float gg_ = tanhf(pre[2]);
        float go_ = sigm(pre[3]);
        float cn = gf_ * c_reg + gi_ * gg_;
        c_reg = cn;

        {
            float s1 = cn, s2 = cn * cn;
            #pragma unroll
            for (int off = 16; off; off >>= 1) {
                s1 += __shfl_xor_sync(0xffffffffu, s1, off);
                s2 += __shfl_xor_sync(0xffffffffu, s2, off);
            }
            int w = tid >> 5;
            if ((tid & 31) == 0) { s.csum[w] = s1; s.csq[w] = s2; }
        }
        __syncthreads();
        if (tid < 4) {
            float S = s.csum[2 * tid] + s.csum[2 * tid + 1];
            float Q = s.csq[2 * tid] + s.csq[2 * tid + 1];
            float mu = S * (1.0f / 64.0f);
            float var = Q * (1.0f / 64.0f) - mu * mu;
            float rs = rsqrtf(var + BN_EPS);
            float sc = rs * s.gc[tid];
            s.cscale[tid] = sc; s.cshift[tid] = s.bc[tid] - mu * sc;
        }
        __syncthreads();

        float hv = go_ * tanhf(cn * s.cscale[jj] + s.cshift[jj]);
        int hrow = j0 + jj;
        g_h[1 - p][hrow * BSZ + col] = hv;
        out[(size_t)t * (HSZ * BSZ) + hrow * BSZ + col] = hv;

        grid_barrier();
    }
}

// ---------------- launch ----------------
extern "C" void kernel_launch(void* const* d_in, const int* in_sizes, int n_in,
                              void* d_out, int out_size) {
    const float* x    = (const float*)d_in[0];
    const float* wih  = (const float*)d_in[1];
    const float* whh  = (const float*)d_in[2];
    const float* bias = (const float*)d_in[3];
    const float* gih  = (const float*)d_in[4];
    const float* bih  = (const float*)d_in[5];
    const float* ghh  = (const float*)d_in[6];
    const float* bhh  = (const float*)d_in[7];
    const float* gcc  = (const float*)d_in[8];
    const float* bcc  = (const float*)d_in[9];
    float* out = (float*)d_out;

    cudaFuncSetAttribute(bn_lstm_kernel,
                         cudaFuncAttributeMaxDynamicSharedMemorySize,
                         (int)sizeof(Smem));
    bn_lstm_kernel<<<NB, TPB, sizeof(Smem)>>>(x, wih, whh, bias, gih, bih,
                                              ghh, bhh, gcc, bcc, out);
}